// round 6
// baseline (speedup 1.0000x reference)
#include <cuda_runtime.h>
#include <stdint.h>

// ---------------------------------------------------------------------------
// Multires hash-grid encode (instant-NGP style), 2D, 16 levels, F=2.
// R2: 4 threads per point (4 levels each) -> fewer live regs, higher occupancy,
// contiguous 32B stores per thread, streaming store hint to protect L2 table.
// ---------------------------------------------------------------------------

#define NUM_LEVELS   16
#define START_HASH   6
#define N_ENTRIES    524309ULL
#define PS1          19349663ULL

// floor(2^64 / 524309) (m odd => floor((2^64-1)/m) == floor(2^64/m))
#define MAGIC_M      (0xFFFFFFFFFFFFFFFFULL / N_ENTRIES)

__device__ __constant__ int c_off[NUM_LEVELS] =
    {0,289,1378,5603,22244,88293,351462,875771,
     1400080,1924389,2448698,2973007,3497316,4021625,4545934,5070243};

__device__ __forceinline__ int mod_prime(unsigned long long h) {
    unsigned long long q = __umul64hi(h, MAGIC_M);
    unsigned long long r = h - q * N_ENTRIES;
    if (r >= N_ENTRIES) r -= N_ENTRIES;
    return (int)r;
}

__global__ __launch_bounds__(256, 5) void hashgrid_kernel(
    const float* __restrict__ x,      // [N,2]
    const float* __restrict__ data,   // [TABLE_SIZE,2]
    float* __restrict__ out,          // [N,32]
    int n)
{
    const int t  = blockIdx.x * blockDim.x + threadIdx.x;
    const int pt = t >> 2;            // point index
    const int g  = t & 3;             // level group: levels [4g, 4g+4)
    if (pt >= n) return;

    const float2 p = reinterpret_cast<const float2*>(x)[pt];
    const float2* __restrict__ tab = reinterpret_cast<const float2*>(data);

    const int base = g << 2;
    int offs[4];
    #pragma unroll
    for (int k = 0; k < 4; ++k) offs[k] = c_off[base + k];

    float acc[8];

    #pragma unroll
    for (int k = 0; k < 4; ++k) {
        const int level = base + k;
        const int res   = 16 << level;
        const float scale = (float)res;
        const float fx = p.x * scale;
        const float fy = p.y * scale;

        // Replicate reference exactly: trunc in fp32; hi corner = trunc(fx+1.0f)
        const int x0 = (int)fx;
        const int y0 = (int)fy;
        const int x1 = (int)(fx + 1.0f);
        const int y1 = (int)(fy + 1.0f);

        const float tx = fx - (float)x0;   // exact: fx < 2^23
        const float ty = fy - (float)y0;

        int i00, i01, i10, i11;
        if (level < START_HASH) {
            const int r1 = res + 1;
            const int a0 = x0 * r1;
            const int a1 = x1 * r1;
            i00 = a0 + y0;
            i01 = a0 + y1;
            i10 = a1 + y0;
            i11 = a1 + y1;
        } else {
            const unsigned long long hy0 = (unsigned long long)(unsigned)y0 * PS1;
            const unsigned long long hy1 = (unsigned long long)(unsigned)y1 * PS1;
            const unsigned long long ux0 = (unsigned)x0;
            const unsigned long long ux1 = (unsigned)x1;
            i00 = mod_prime(ux0 ^ hy0);
            i01 = mod_prime(ux0 ^ hy1);
            i10 = mod_prime(ux1 ^ hy0);
            i11 = mod_prime(ux1 ^ hy1);
        }
        const int off = offs[k];

        // all 4 gathers back-to-back for MLP
        const float2 v00 = __ldg(&tab[i00 + off]);
        const float2 v01 = __ldg(&tab[i01 + off]);
        const float2 v10 = __ldg(&tab[i10 + off]);
        const float2 v11 = __ldg(&tab[i11 + off]);

        const float wx0 = 1.0f - tx, wx1 = tx;
        const float wy0 = 1.0f - ty, wy1 = ty;
        const float w00 = wx0 * wy0;
        const float w01 = wx0 * wy1;
        const float w10 = wx1 * wy0;
        const float w11 = wx1 * wy1;

        float f0 = w00 * v00.x;
        f0 = fmaf(w01, v01.x, f0);
        f0 = fmaf(w10, v10.x, f0);
        f0 = fmaf(w11, v11.x, f0);
        float f1 = w00 * v00.y;
        f1 = fmaf(w01, v01.y, f1);
        f1 = fmaf(w10, v10.y, f1);
        f1 = fmaf(w11, v11.y, f1);

        acc[2 * k]     = f0;
        acc[2 * k + 1] = f1;
    }

    // Each thread writes its contiguous 32B slice; 4 lanes of one point form a
    // contiguous 128B row. Streaming hint: don't let output evict the table in L2.
    float4* o = reinterpret_cast<float4*>(out + (size_t)pt * 32 + (base << 1));
    __stcs(o,     make_float4(acc[0], acc[1], acc[2], acc[3]));
    __stcs(o + 1, make_float4(acc[4], acc[5], acc[6], acc[7]));
}

extern "C" void kernel_launch(void* const* d_in, const int* in_sizes, int n_in,
                              void* d_out, int out_size) {
    const float* x    = (const float*)d_in[0];   // [N,2] fp32
    const float* data = (const float*)d_in[1];   // [TABLE_SIZE,2] fp32
    float* out        = (float*)d_out;           // [N,32] fp32

    const int n = in_sizes[0] / 2;               // number of points
    const int threads = 256;
    const long long total = 4LL * n;             // 4 threads per point
    const int blocks = (int)((total + threads - 1) / threads);
    hashgrid_kernel<<<blocks, threads>>>(x, data, out, n);
}

// round 8
// speedup vs baseline: 1.3349x; 1.3349x over previous
#include <cuda_runtime.h>
#include <stdint.h>

// ---------------------------------------------------------------------------
// Multires hash-grid encode (instant-NGP style), 2D, 16 levels, F=2.
// R6: back to 1 thread/point (compile-time level branches, intra-warp gather
// locality). Levels 0-2 tables cached in shared memory (44.8KB). Output staged
// through the same smem region (stride-33 padded) for fully coalesced stores.
// ---------------------------------------------------------------------------

#define NUM_LEVELS   16
#define START_HASH   6
#define N_ENTRIES    524309ULL
#define PS1          19349663ULL
#define SMEM_LEVELS  3          // levels 0..2 cached in shared (5603 entries)
#define SMEM_ENTRIES 5603

// floor(2^64 / 524309) (m odd => floor((2^64-1)/m) == floor(2^64/m))
#define MAGIC_M      (0xFFFFFFFFFFFFFFFFULL / N_ENTRIES)

__device__ __constant__ int c_off[NUM_LEVELS] =
    {0,289,1378,5603,22244,88293,351462,875771,
     1400080,1924389,2448698,2973007,3497316,4021625,4545934,5070243};

__device__ __forceinline__ int mod_prime(unsigned long long h) {
    unsigned long long q = __umul64hi(h, MAGIC_M);
    unsigned long long r = h - q * N_ENTRIES;
    if (r >= N_ENTRIES) r -= N_ENTRIES;
    return (int)r;
}

// smem: phase A = level 0-2 table (5603 float2 = 11206 floats = 44824B)
//       phase B = output staging (256 pts * 33 floats = 8448 floats, padded)
#define SMEM_FLOATS 11206

__global__ __launch_bounds__(256, 4) void hashgrid_kernel(
    const float* __restrict__ x,      // [N,2]
    const float* __restrict__ data,   // [TABLE_SIZE,2]
    float* __restrict__ out,          // [N,32]
    int n)
{
    __shared__ __align__(16) float smem[SMEM_FLOATS];

    const int tid        = threadIdx.x;
    const int blockStart = blockIdx.x * 256;
    const int pt         = blockStart + tid;
    const bool valid     = (pt < n);

    const float2* __restrict__ tab = reinterpret_cast<const float2*>(data);
    float2* sm2 = reinterpret_cast<float2*>(smem);

    // ---- Phase A0: cooperative load of level 0-2 tables into smem ----------
    for (int e = tid; e < SMEM_ENTRIES; e += 256)
        sm2[e] = __ldg(&tab[e]);
    __syncthreads();

    float2 p = make_float2(0.0f, 0.0f);
    if (valid) p = reinterpret_cast<const float2*>(x)[pt];

    float acc[2 * NUM_LEVELS];

    // ---- Phase A1: all 16 levels, fully unrolled (compile-time branches) ---
    #pragma unroll
    for (int l = 0; l < NUM_LEVELS; ++l) {
        const int res = 16 << l;
        const float scale = (float)res;
        const float fx = p.x * scale;
        const float fy = p.y * scale;

        // Replicate reference exactly: trunc in fp32; hi corner = trunc(fx+1.0f)
        const int x0 = (int)fx;
        const int y0 = (int)fy;
        const int x1 = (int)(fx + 1.0f);
        const int y1 = (int)(fy + 1.0f);

        const float tx = fx - (float)x0;   // exact: fx < 2^23
        const float ty = fy - (float)y0;

        float2 v00, v01, v10, v11;
        if (l < SMEM_LEVELS) {
            const int r1 = res + 1;
            const int a0 = x0 * r1 + c_off[l];
            const int a1 = x1 * r1 + c_off[l];
            v00 = sm2[a0 + y0];
            v01 = sm2[a0 + y1];
            v10 = sm2[a1 + y0];
            v11 = sm2[a1 + y1];
        } else if (l < START_HASH) {
            const int r1 = res + 1;
            const int a0 = x0 * r1 + c_off[l];
            const int a1 = x1 * r1 + c_off[l];
            v00 = __ldg(&tab[a0 + y0]);
            v01 = __ldg(&tab[a0 + y1]);
            v10 = __ldg(&tab[a1 + y0]);
            v11 = __ldg(&tab[a1 + y1]);
        } else {
            const unsigned long long hy0 = (unsigned long long)(unsigned)y0 * PS1;
            const unsigned long long hy1 = (unsigned long long)(unsigned)y1 * PS1;
            const unsigned long long ux0 = (unsigned)x0;
            const unsigned long long ux1 = (unsigned)x1;
            const int off = c_off[l];
            const int i00 = mod_prime(ux0 ^ hy0) + off;
            const int i01 = mod_prime(ux0 ^ hy1) + off;
            const int i10 = mod_prime(ux1 ^ hy0) + off;
            const int i11 = mod_prime(ux1 ^ hy1) + off;
            v00 = __ldg(&tab[i00]);
            v01 = __ldg(&tab[i01]);
            v10 = __ldg(&tab[i10]);
            v11 = __ldg(&tab[i11]);
        }

        const float wx0 = 1.0f - tx, wx1 = tx;
        const float wy0 = 1.0f - ty, wy1 = ty;
        const float w00 = wx0 * wy0;
        const float w01 = wx0 * wy1;
        const float w10 = wx1 * wy0;
        const float w11 = wx1 * wy1;

        float f0 = w00 * v00.x;
        f0 = fmaf(w01, v01.x, f0);
        f0 = fmaf(w10, v10.x, f0);
        f0 = fmaf(w11, v11.x, f0);
        float f1 = w00 * v00.y;
        f1 = fmaf(w01, v01.y, f1);
        f1 = fmaf(w10, v10.y, f1);
        f1 = fmaf(w11, v11.y, f1);

        acc[2 * l]     = f0;
        acc[2 * l + 1] = f1;
    }

    // ---- Phase B: stage results in smem (stride 33 -> conflict-free), then
    //      write fully coalesced 128B rows. ---------------------------------
    __syncthreads();   // all smem-table reads complete before overwrite

    #pragma unroll
    for (int j = 0; j < 32; ++j)
        smem[tid * 33 + j] = acc[j];
    __syncthreads();

    const size_t outBase = (size_t)blockStart * 32;
    int limit = 8192;
    if (blockStart + 256 > n) limit = (n - blockStart) * 32;   // partial tail block
    if (limit < 0) limit = 0;

    for (int k = tid; k < limit; k += 256) {
        const int pp = k >> 5;
        const int j  = k & 31;
        __stcs(&out[outBase + k], smem[pp * 33 + j]);
    }
}

extern "C" void kernel_launch(void* const* d_in, const int* in_sizes, int n_in,
                              void* d_out, int out_size) {
    const float* x    = (const float*)d_in[0];   // [N,2] fp32
    const float* data = (const float*)d_in[1];   // [TABLE_SIZE,2] fp32
    float* out        = (float*)d_out;           // [N,32] fp32

    const int n = in_sizes[0] / 2;               // number of points
    const int threads = 256;
    const int blocks  = (n + threads - 1) / threads;
    hashgrid_kernel<<<blocks, threads>>>(x, data, out, n);
}

// round 9
// speedup vs baseline: 1.5349x; 1.1498x over previous
#include <cuda_runtime.h>
#include <stdint.h>

// ---------------------------------------------------------------------------
// Multires hash-grid encode (instant-NGP style), 2D, 16 levels, F=2.
// R8: warp-pair level split. Block = 256 thr = 128 points; even warps compute
// levels {0,2,..,14}, odd warps {1,3,..,15} for the same 32 points. Results go
// straight to padded smem (no per-thread acc array -> low regs -> high occ),
// then coalesced streaming stores. Grid/hash branch is compile-time per k.
// ---------------------------------------------------------------------------

#define NUM_LEVELS   16
#define START_HASH   6
#define N_ENTRIES    524309ULL
#define PS1          19349663ULL

// floor(2^64 / 524309) (m odd => floor((2^64-1)/m) == floor(2^64/m))
#define MAGIC_M      (0xFFFFFFFFFFFFFFFFULL / N_ENTRIES)

#define PTS_PER_BLOCK 128
#define STRIDE        33            // padded row stride (floats) -> conflict-free

__device__ __constant__ int c_off[NUM_LEVELS] =
    {0,289,1378,5603,22244,88293,351462,875771,
     1400080,1924389,2448698,2973007,3497316,4021625,4545934,5070243};

__device__ __forceinline__ int mod_prime(unsigned long long h) {
    unsigned long long q = __umul64hi(h, MAGIC_M);
    unsigned long long r = h - q * N_ENTRIES;
    if (r >= N_ENTRIES) r -= N_ENTRIES;
    return (int)r;
}

__global__ __launch_bounds__(256, 6) void hashgrid_kernel(
    const float* __restrict__ x,      // [N,2]
    const float* __restrict__ data,   // [TABLE_SIZE,2]
    float* __restrict__ out,          // [N,32]
    int n)
{
    __shared__ __align__(16) float stage[PTS_PER_BLOCK * STRIDE];  // 16896 B

    const int tid  = threadIdx.x;
    const int warp = tid >> 5;
    const int lane = tid & 31;
    const int e    = warp & 1;                 // level parity this warp handles
    const int pw   = ((warp >> 1) << 5) + lane; // point index within block 0..127

    const int blockStart = blockIdx.x * PTS_PER_BLOCK;
    const int pt = blockStart + pw;

    const float2* __restrict__ tab = reinterpret_cast<const float2*>(data);

    if (pt < n) {
        const float2 p = reinterpret_cast<const float2*>(x)[pt];
        float* srow = &stage[pw * STRIDE];

        #pragma unroll
        for (int k = 0; k < 8; ++k) {
            // level l = 2k + e   (e is warp-uniform runtime 0/1)
            const int l   = (k << 1) + e;
            const int res = 16 << l;                 // uniform shift
            const float scale = (float)res;
            const float fx = p.x * scale;
            const float fy = p.y * scale;

            // Match reference exactly: trunc fp32; hi corner = trunc(fx+1.0f)
            const int x0 = (int)fx;
            const int y0 = (int)fy;
            const int x1 = (int)(fx + 1.0f);
            const int y1 = (int)(fy + 1.0f);

            const float tx = fx - (float)x0;   // exact: fx < 2^23
            const float ty = fy - (float)y0;

            float2 v00, v01, v10, v11;
            if (k < 3) {
                // l in {0..5}: dense grid (compile-time branch)
                const int r1  = res + 1;
                const int off = c_off[l];
                const int a0  = x0 * r1 + off;
                const int a1  = x1 * r1 + off;
                v00 = __ldg(&tab[a0 + y0]);
                v01 = __ldg(&tab[a0 + y1]);
                v10 = __ldg(&tab[a1 + y0]);
                v11 = __ldg(&tab[a1 + y1]);
            } else {
                // l in {6..15}: spatial hash (compile-time branch)
                const unsigned long long hy0 = (unsigned long long)(unsigned)y0 * PS1;
                const unsigned long long hy1 = (unsigned long long)(unsigned)y1 * PS1;
                const unsigned long long ux0 = (unsigned)x0;
                const unsigned long long ux1 = (unsigned)x1;
                const int off = c_off[l];
                const int i00 = mod_prime(ux0 ^ hy0) + off;
                const int i01 = mod_prime(ux0 ^ hy1) + off;
                const int i10 = mod_prime(ux1 ^ hy0) + off;
                const int i11 = mod_prime(ux1 ^ hy1) + off;
                v00 = __ldg(&tab[i00]);
                v01 = __ldg(&tab[i01]);
                v10 = __ldg(&tab[i10]);
                v11 = __ldg(&tab[i11]);
            }

            const float wx0 = 1.0f - tx, wx1 = tx;
            const float wy0 = 1.0f - ty, wy1 = ty;
            const float w00 = wx0 * wy0;
            const float w01 = wx0 * wy1;
            const float w10 = wx1 * wy0;
            const float w11 = wx1 * wy1;

            float f0 = w00 * v00.x;
            f0 = fmaf(w01, v01.x, f0);
            f0 = fmaf(w10, v10.x, f0);
            f0 = fmaf(w11, v11.x, f0);
            float f1 = w00 * v00.y;
            f1 = fmaf(w01, v01.y, f1);
            f1 = fmaf(w10, v10.y, f1);
            f1 = fmaf(w11, v11.y, f1);

            // write straight to staging smem (no acc array -> low reg pressure)
            srow[(l << 1)]     = f0;
            srow[(l << 1) + 1] = f1;
        }
    }
    __syncthreads();

    // coalesced streaming stores: 128 pts * 32 floats = 4096 floats / block
    const size_t outBase = (size_t)blockStart * 32;
    int limit = PTS_PER_BLOCK * 32;
    if (blockStart + PTS_PER_BLOCK > n) {
        limit = (n - blockStart) * 32;
        if (limit < 0) limit = 0;
    }
    for (int idx = tid; idx < limit; idx += 256) {
        const int pp = idx >> 5;
        const int j  = idx & 31;
        __stcs(&out[outBase + idx], stage[pp * STRIDE + j]);
    }
}

extern "C" void kernel_launch(void* const* d_in, const int* in_sizes, int n_in,
                              void* d_out, int out_size) {
    const float* x    = (const float*)d_in[0];   // [N,2] fp32
    const float* data = (const float*)d_in[1];   // [TABLE_SIZE,2] fp32
    float* out        = (float*)d_out;           // [N,32] fp32

    const int n = in_sizes[0] / 2;               // number of points
    const int blocks = (n + PTS_PER_BLOCK - 1) / PTS_PER_BLOCK;
    hashgrid_kernel<<<blocks, 256>>>(x, data, out, n);
}

// round 12
// speedup vs baseline: 1.5725x; 1.0245x over previous
#include <cuda_runtime.h>
#include <stdint.h>

// ---------------------------------------------------------------------------
// Multires hash-grid encode (instant-NGP style), 2D, 16 levels, F=2.
// R9: 4-way warp-level level split. Block = 256 thr = 8 warps = 2 groups of
// 32 points; warp e in {0..3} of each group computes levels {e,e+4,e+8,e+12}
// for its 32 points. Branches warp-uniform, gather locality preserved, only
// 4 levels of live state per thread -> <=32 regs -> 64 warps/SM.
// ---------------------------------------------------------------------------

#define NUM_LEVELS   16
#define START_HASH   6
#define N_ENTRIES    524309ULL
#define PS1          19349663ULL

// floor(2^64 / 524309) (m odd => floor((2^64-1)/m) == floor(2^64/m))
#define MAGIC_M      (0xFFFFFFFFFFFFFFFFULL / N_ENTRIES)

#define PTS_PER_BLOCK 64
#define STRIDE        33            // padded row stride (floats) -> conflict-free

__device__ __constant__ int c_off[NUM_LEVELS] =
    {0,289,1378,5603,22244,88293,351462,875771,
     1400080,1924389,2448698,2973007,3497316,4021625,4545934,5070243};

__device__ __forceinline__ int mod_prime(unsigned long long h) {
    unsigned long long q = __umul64hi(h, MAGIC_M);
    unsigned long long r = h - q * N_ENTRIES;
    if (r >= N_ENTRIES) r -= N_ENTRIES;
    return (int)r;
}

__global__ __launch_bounds__(256, 8) void hashgrid_kernel(
    const float* __restrict__ x,      // [N,2]
    const float* __restrict__ data,   // [TABLE_SIZE,2]
    float* __restrict__ out,          // [N,32]
    int n)
{
    __shared__ __align__(16) float stage[PTS_PER_BLOCK * STRIDE];  // 8448 B

    const int tid  = threadIdx.x;
    const int warp = tid >> 5;
    const int lane = tid & 31;
    const int e    = warp & 3;                  // level residue this warp handles
    const int pw   = ((warp >> 2) << 5) + lane; // point index within block 0..63

    const int blockStart = blockIdx.x * PTS_PER_BLOCK;
    const int pt = blockStart + pw;

    const float2* __restrict__ tab = reinterpret_cast<const float2*>(data);

    if (pt < n) {
        const float2 p = reinterpret_cast<const float2*>(x)[pt];
        float* srow = &stage[pw * STRIDE];

        #pragma unroll
        for (int k = 0; k < 4; ++k) {
            // level l = 4k + e   (e is warp-uniform runtime 0..3)
            const int l   = (k << 2) + e;
            const int res = 16 << l;
            const float scale = (float)res;
            const float fx = p.x * scale;
            const float fy = p.y * scale;

            // Match reference exactly: trunc fp32; hi corner = trunc(fx+1.0f)
            const int x0 = (int)fx;
            const int y0 = (int)fy;
            const int x1 = (int)(fx + 1.0f);
            const int y1 = (int)(fy + 1.0f);

            const float tx = fx - (float)x0;   // exact: fx < 2^23
            const float ty = fy - (float)y0;

            float2 v00, v01, v10, v11;
            // k=0 -> always grid; k=1 -> grid iff e<2 (warp-uniform);
            // k>=2 -> always hash. No lane divergence anywhere.
            if (k == 0 || (k == 1 && e < 2)) {
                const int r1  = res + 1;
                const int off = c_off[l];
                const int a0  = x0 * r1 + off;
                const int a1  = x1 * r1 + off;
                v00 = __ldg(&tab[a0 + y0]);
                v01 = __ldg(&tab[a0 + y1]);
                v10 = __ldg(&tab[a1 + y0]);
                v11 = __ldg(&tab[a1 + y1]);
            } else {
                const unsigned long long hy0 = (unsigned long long)(unsigned)y0 * PS1;
                const unsigned long long hy1 = (unsigned long long)(unsigned)y1 * PS1;
                const unsigned long long ux0 = (unsigned)x0;
                const unsigned long long ux1 = (unsigned)x1;
                const int off = c_off[l];
                const int i00 = mod_prime(ux0 ^ hy0) + off;
                const int i01 = mod_prime(ux0 ^ hy1) + off;
                const int i10 = mod_prime(ux1 ^ hy0) + off;
                const int i11 = mod_prime(ux1 ^ hy1) + off;
                v00 = __ldg(&tab[i00]);
                v01 = __ldg(&tab[i01]);
                v10 = __ldg(&tab[i10]);
                v11 = __ldg(&tab[i11]);
            }

            const float wx0 = 1.0f - tx, wx1 = tx;
            const float wy0 = 1.0f - ty, wy1 = ty;
            const float w00 = wx0 * wy0;
            const float w01 = wx0 * wy1;
            const float w10 = wx1 * wy0;
            const float w11 = wx1 * wy1;

            float f0 = w00 * v00.x;
            f0 = fmaf(w01, v01.x, f0);
            f0 = fmaf(w10, v10.x, f0);
            f0 = fmaf(w11, v11.x, f0);
            float f1 = w00 * v00.y;
            f1 = fmaf(w01, v01.y, f1);
            f1 = fmaf(w10, v10.y, f1);
            f1 = fmaf(w11, v11.y, f1);

            // straight to staging smem (no acc array -> low reg pressure)
            srow[(l << 1)]     = f0;
            srow[(l << 1) + 1] = f1;
        }
    }
    __syncthreads();

    // coalesced streaming stores: 64 pts * 32 floats = 2048 floats / block
    const size_t outBase = (size_t)blockStart * 32;
    int limit = PTS_PER_BLOCK * 32;
    if (blockStart + PTS_PER_BLOCK > n) {
        limit = (n - blockStart) * 32;
        if (limit < 0) limit = 0;
    }
    #pragma unroll
    for (int idx = tid; idx < limit; idx += 256) {
        const int pp = idx >> 5;
        const int j  = idx & 31;
        __stcs(&out[outBase + idx], stage[pp * STRIDE + j]);
    }
}

extern "C" void kernel_launch(void* const* d_in, const int* in_sizes, int n_in,
                              void* d_out, int out_size) {
    const float* x    = (const float*)d_in[0];   // [N,2] fp32
    const float* data = (const float*)d_in[1];   // [TABLE_SIZE,2] fp32
    float* out        = (float*)d_out;           // [N,32] fp32

    const int n = in_sizes[0] / 2;               // number of points
    const int blocks = (n + PTS_PER_BLOCK - 1) / PTS_PER_BLOCK;
    hashgrid_kernel<<<blocks, 256>>>(x, data, out, n);
}

// round 13
// speedup vs baseline: 1.6317x; 1.0376x over previous
#include <cuda_runtime.h>
#include <stdint.h>

// ---------------------------------------------------------------------------
// Multires hash-grid encode (instant-NGP style), 2D, 16 levels, F=2.
// R12: R9 structure (4-way warp-level split, 64 pts/block, 8 warps, <=32 regs,
// 8 CTAs/SM) + shared-memory cache of level 0-1 tables (1378 entries, 11KB).
// Levels 0-1 gathers cost ~18-28 L1tex wavefronts each as random global loads;
// as LDS they cost ~4 cyc. Total smem 19.7KB/CTA keeps 8 CTAs resident.
// ---------------------------------------------------------------------------

#define NUM_LEVELS   16
#define START_HASH   6
#define N_ENTRIES    524309ULL
#define PS1          19349663ULL

// floor(2^64 / 524309) (m odd => floor((2^64-1)/m) == floor(2^64/m))
#define MAGIC_M      (0xFFFFFFFFFFFFFFFFULL / N_ENTRIES)

#define PTS_PER_BLOCK 64
#define STRIDE        33            // padded row stride (floats) -> conflict-free
#define SMTAB_ENTRIES 1378          // levels 0 (289) + 1 (1089)

__device__ __constant__ int c_off[NUM_LEVELS] =
    {0,289,1378,5603,22244,88293,351462,875771,
     1400080,1924389,2448698,2973007,3497316,4021625,4545934,5070243};

__device__ __forceinline__ int mod_prime(unsigned long long h) {
    unsigned long long q = __umul64hi(h, MAGIC_M);
    unsigned long long r = h - q * N_ENTRIES;
    if (r >= N_ENTRIES) r -= N_ENTRIES;
    return (int)r;
}

__global__ __launch_bounds__(256, 8) void hashgrid_kernel(
    const float* __restrict__ x,      // [N,2]
    const float* __restrict__ data,   // [TABLE_SIZE,2]
    float* __restrict__ out,          // [N,32]
    int n)
{
    __shared__ __align__(16) float2 smtab[SMTAB_ENTRIES];          // 11024 B
    __shared__ __align__(16) float  stage[PTS_PER_BLOCK * STRIDE]; //  8448 B

    const int tid  = threadIdx.x;
    const int warp = tid >> 5;
    const int lane = tid & 31;
    const int e    = warp & 3;                  // level residue this warp handles
    const int pw   = ((warp >> 2) << 5) + lane; // point index within block 0..63

    const int blockStart = blockIdx.x * PTS_PER_BLOCK;
    const int pt = blockStart + pw;

    const float2* __restrict__ tab = reinterpret_cast<const float2*>(data);

    // cooperative fill of level 0-1 tables (coalesced, ~87 lines/block)
    for (int t = tid; t < SMTAB_ENTRIES; t += 256)
        smtab[t] = __ldg(&tab[t]);
    __syncthreads();

    if (pt < n) {
        const float2 p = reinterpret_cast<const float2*>(x)[pt];
        float* srow = &stage[pw * STRIDE];

        #pragma unroll
        for (int k = 0; k < 4; ++k) {
            // level l = 4k + e   (e is warp-uniform runtime 0..3)
            const int l   = (k << 2) + e;
            const int res = 16 << l;
            const float scale = (float)res;
            const float fx = p.x * scale;
            const float fy = p.y * scale;

            // Match reference exactly: trunc fp32; hi corner = trunc(fx+1.0f)
            const int x0 = (int)fx;
            const int y0 = (int)fy;
            const int x1 = (int)(fx + 1.0f);
            const int y1 = (int)(fy + 1.0f);

            const float tx = fx - (float)x0;   // exact: fx < 2^23
            const float ty = fy - (float)y0;

            float2 v00, v01, v10, v11;
            // All branches warp-uniform; no lane divergence anywhere.
            if (k == 0 && e < 2) {
                // levels 0,1: smem-cached dense grid (offsets 0 / 289 match global)
                const int r1  = res + 1;
                const int a0  = x0 * r1 + c_off[l];
                const int a1  = x1 * r1 + c_off[l];
                v00 = smtab[a0 + y0];
                v01 = smtab[a0 + y1];
                v10 = smtab[a1 + y0];
                v11 = smtab[a1 + y1];
            } else if (k == 0 || (k == 1 && e < 2)) {
                // levels 2,3,4,5: dense grid from global
                const int r1  = res + 1;
                const int off = c_off[l];
                const int a0  = x0 * r1 + off;
                const int a1  = x1 * r1 + off;
                v00 = __ldg(&tab[a0 + y0]);
                v01 = __ldg(&tab[a0 + y1]);
                v10 = __ldg(&tab[a1 + y0]);
                v11 = __ldg(&tab[a1 + y1]);
            } else {
                // levels 6..15: spatial hash
                const unsigned long long hy0 = (unsigned long long)(unsigned)y0 * PS1;
                const unsigned long long hy1 = (unsigned long long)(unsigned)y1 * PS1;
                const unsigned long long ux0 = (unsigned)x0;
                const unsigned long long ux1 = (unsigned)x1;
                const int off = c_off[l];
                const int i00 = mod_prime(ux0 ^ hy0) + off;
                const int i01 = mod_prime(ux0 ^ hy1) + off;
                const int i10 = mod_prime(ux1 ^ hy0) + off;
                const int i11 = mod_prime(ux1 ^ hy1) + off;
                v00 = __ldg(&tab[i00]);
                v01 = __ldg(&tab[i01]);
                v10 = __ldg(&tab[i10]);
                v11 = __ldg(&tab[i11]);
            }

            const float wx0 = 1.0f - tx, wx1 = tx;
            const float wy0 = 1.0f - ty, wy1 = ty;
            const float w00 = wx0 * wy0;
            const float w01 = wx0 * wy1;
            const float w10 = wx1 * wy0;
            const float w11 = wx1 * wy1;

            float f0 = w00 * v00.x;
            f0 = fmaf(w01, v01.x, f0);
            f0 = fmaf(w10, v10.x, f0);
            f0 = fmaf(w11, v11.x, f0);
            float f1 = w00 * v00.y;
            f1 = fmaf(w01, v01.y, f1);
            f1 = fmaf(w10, v10.y, f1);
            f1 = fmaf(w11, v11.y, f1);

            // straight to staging smem (no acc array -> low reg pressure)
            srow[(l << 1)]     = f0;
            srow[(l << 1) + 1] = f1;
        }
    }
    __syncthreads();

    // coalesced streaming stores: 64 pts * 32 floats = 2048 floats / block
    const size_t outBase = (size_t)blockStart * 32;
    int limit = PTS_PER_BLOCK * 32;
    if (blockStart + PTS_PER_BLOCK > n) {
        limit = (n - blockStart) * 32;
        if (limit < 0) limit = 0;
    }
    #pragma unroll
    for (int idx = tid; idx < limit; idx += 256) {
        const int pp = idx >> 5;
        const int j  = idx & 31;
        __stcs(&out[outBase + idx], stage[pp * STRIDE + j]);
    }
}

extern "C" void kernel_launch(void* const* d_in, const int* in_sizes, int n_in,
                              void* d_out, int out_size) {
    const float* x    = (const float*)d_in[0];   // [N,2] fp32
    const float* data = (const float*)d_in[1];   // [TABLE_SIZE,2] fp32
    float* out        = (float*)d_out;           // [N,32] fp32

    const int n = in_sizes[0] / 2;               // number of points
    const int blocks = (n + PTS_PER_BLOCK - 1) / PTS_PER_BLOCK;
    hashgrid_kernel<<<blocks, 256>>>(x, data, out, n);
}